// round 10
// baseline (speedup 1.0000x reference)
#include <cuda_runtime.h>
#include <cuda_bf16.h>
#include <cstdint>

// Problem constants
#define Bn 64
#define Sn 512
#define Dn 256
#define Hn 256
#define Ln 9

// ---------------------------------------------------------------------------
// Static device scratch
// ---------------------------------------------------------------------------
__device__ float g_Xperm[2u * 512u * 64u * 1024u];      // 268 MB
__device__ float g_Hbuf[2u * 512u * 64u * 256u];        // 67 MB
__device__ float g_hstate[2][2][Bn * Hn];               // [parity][dir]
__device__ float g_em[(size_t)Bn * Sn * Ln];
__device__ float g_res[Bn];
// Split barrier counters: 8 per direction, each on its own 128B line.
__device__ unsigned g_cnt[2][8][32];
__device__ unsigned g_exit[2];

__device__ __forceinline__ float fsig(float x) { return 1.0f / (1.0f + __expf(-x)); }
__device__ __forceinline__ float ftanh(float x) { return 2.0f / (1.0f + __expf(-2.0f * x)) - 1.0f; }

// Packed f32x2 FMA (sm_100+): d = a*b + d, lane-wise on 2 packed floats.
__device__ __forceinline__ void ffma2(unsigned long long& d,
                                      unsigned long long a,
                                      unsigned long long b) {
    asm("fma.rn.f32x2 %0, %1, %2, %0;" : "+l"(d) : "l"(a), "l"(b));
}
__device__ __forceinline__ unsigned long long dup2(float x) {
    unsigned long long r;
    asm("mov.b64 %0, {%1, %1};" : "=l"(r) : "f"(x));
    return r;
}
__device__ __forceinline__ float hsum2(unsigned long long p) {
    float lo, hi;
    asm("mov.b64 {%0, %1}, %2;" : "=f"(lo), "=f"(hi) : "l"(p));
    return lo + hi;
}

// ---------------------------------------------------------------------------
// Dummy kernels: shift the ncu capture slot onto the recurrence kernel.
// ---------------------------------------------------------------------------
__global__ void dummy_kernel() {}

// ---------------------------------------------------------------------------
// Kernel 1: embedding gather + input projection GEMM (+bias), permuted write.
// Tile 64m x 128n, K-chunk 16, 256 threads, 4x8 micro-tile, packed FFMA2.
// grid = (8 n-tiles, 512 s, 2 dirs)
// ---------------------------------------------------------------------------
__global__ void embed_inproj_kernel(const int* __restrict__ x,
                                    const float* __restrict__ E,
                                    const float* __restrict__ Wih_f,
                                    const float* __restrict__ b_f,
                                    const float* __restrict__ Wih_b,
                                    const float* __restrict__ b_b) {
    const int dir = blockIdx.z;
    const float* __restrict__ W = dir ? Wih_b : Wih_f;
    const float* __restrict__ bias = dir ? b_b : b_f;
    const int s = blockIdx.y;
    const int n0 = blockIdx.x * 128;

    __shared__ float sA[16][68];     // A^T: [k][m], 64 m + pad
    __shared__ float sB[16][132];    // B^T: [k][n], 128 n + pad
    __shared__ int srow[64];

    const int tid = threadIdx.x;
    if (tid < 64) srow[tid] = x[tid * Sn + s];
    __syncthreads();

    const int tm = tid & 15;          // 4 m-rows: 4*tm..
    const int tn = tid >> 4;          // 8 n-cols: 8*tn..
    const int lrow = tid >> 2;        // loader row 0..63
    const int kq = tid & 3;           // loader k-quad

    unsigned long long acc[4][4];     // [m][n-pair], each packs 2 n-values
#pragma unroll
    for (int c = 0; c < 4; c++)
#pragma unroll
        for (int p = 0; p < 4; p++) acc[c][p] = 0ull;

    for (int k0 = 0; k0 < 256; k0 += 16) {
        float4 a4 = *reinterpret_cast<const float4*>(&E[(size_t)srow[lrow] * Dn + k0 + kq * 4]);
        float4 b4 = *reinterpret_cast<const float4*>(&W[(size_t)(n0 + lrow) * Dn + k0 + kq * 4]);
        float4 c4 = *reinterpret_cast<const float4*>(&W[(size_t)(n0 + 64 + lrow) * Dn + k0 + kq * 4]);
        __syncthreads();   // previous compute done reading smem
        sA[kq * 4 + 0][lrow] = a4.x; sA[kq * 4 + 1][lrow] = a4.y;
        sA[kq * 4 + 2][lrow] = a4.z; sA[kq * 4 + 3][lrow] = a4.w;
        sB[kq * 4 + 0][lrow] = b4.x; sB[kq * 4 + 1][lrow] = b4.y;
        sB[kq * 4 + 2][lrow] = b4.z; sB[kq * 4 + 3][lrow] = b4.w;
        sB[kq * 4 + 0][64 + lrow] = c4.x; sB[kq * 4 + 1][64 + lrow] = c4.y;
        sB[kq * 4 + 2][64 + lrow] = c4.z; sB[kq * 4 + 3][64 + lrow] = c4.w;
        __syncthreads();
#pragma unroll
        for (int kk = 0; kk < 16; kk++) {
            float4 ra = *reinterpret_cast<float4*>(&sA[kk][4 * tm]);
            ulonglong2 rb0 = *reinterpret_cast<ulonglong2*>(&sB[kk][8 * tn]);
            ulonglong2 rb1 = *reinterpret_cast<ulonglong2*>(&sB[kk][8 * tn + 4]);
            unsigned long long d0 = dup2(ra.x), d1 = dup2(ra.y);
            unsigned long long d2 = dup2(ra.z), d3 = dup2(ra.w);
            ffma2(acc[0][0], d0, rb0.x); ffma2(acc[0][1], d0, rb0.y);
            ffma2(acc[0][2], d0, rb1.x); ffma2(acc[0][3], d0, rb1.y);
            ffma2(acc[1][0], d1, rb0.x); ffma2(acc[1][1], d1, rb0.y);
            ffma2(acc[1][2], d1, rb1.x); ffma2(acc[1][3], d1, rb1.y);
            ffma2(acc[2][0], d2, rb0.x); ffma2(acc[2][1], d2, rb0.y);
            ffma2(acc[2][2], d2, rb1.x); ffma2(acc[2][3], d2, rb1.y);
            ffma2(acc[3][0], d3, rb0.x); ffma2(acc[3][1], d3, rb0.y);
            ffma2(acc[3][2], d3, rb1.x); ffma2(acc[3][3], d3, rb1.y);
        }
    }

    // Epilogue: add bias, permuted write. n-range: n0 + 8*tn .. +7.
    const int nb = n0 + 8 * tn;
    const int blkA = (nb >> 2) & 63;  const int mgA = nb >> 8;
    const int nb2 = nb + 4;
    const int blkB = (nb2 >> 2) & 63; const int mgB = nb2 >> 8;
    const size_t baseA = (((size_t)dir * Sn + s) * 64 + blkA) * 1024 + (size_t)mgA * 4;
    const size_t baseB = (((size_t)dir * Sn + s) * 64 + blkB) * 1024 + (size_t)mgB * 4;
    float4 biasA = *reinterpret_cast<const float4*>(&bias[nb]);
    float4 biasB = *reinterpret_cast<const float4*>(&bias[nb + 4]);
#pragma unroll
    for (int c = 0; c < 4; c++) {
        const int b = 4 * tm + c;
        float f0, f1, f2, f3, f4, f5, f6, f7;
        asm("mov.b64 {%0, %1}, %2;" : "=f"(f0), "=f"(f1) : "l"(acc[c][0]));
        asm("mov.b64 {%0, %1}, %2;" : "=f"(f2), "=f"(f3) : "l"(acc[c][1]));
        asm("mov.b64 {%0, %1}, %2;" : "=f"(f4), "=f"(f5) : "l"(acc[c][2]));
        asm("mov.b64 {%0, %1}, %2;" : "=f"(f6), "=f"(f7) : "l"(acc[c][3]));
        float4 vA, vB;
        vA.x = f0 + biasA.x; vA.y = f1 + biasA.y; vA.z = f2 + biasA.z; vA.w = f3 + biasA.w;
        vB.x = f4 + biasB.x; vB.y = f5 + biasB.y; vB.z = f6 + biasB.z; vB.w = f7 + biasB.w;
        *reinterpret_cast<float4*>(&g_Xperm[baseA + (size_t)b * 16]) = vA;
        *reinterpret_cast<float4*>(&g_Xperm[baseB + (size_t)b * 16]) = vB;
    }
}

// ---------------------------------------------------------------------------
// Split-counter grid barrier (per direction, 64 blocks).
// ---------------------------------------------------------------------------
__device__ __forceinline__ void dir_barrier(int dir, int blk, unsigned n) {
    __threadfence();
    __syncthreads();
    const int tid = threadIdx.x;
    if (tid == 0) atomicAdd(&g_cnt[dir][blk & 7][0], 1u);
    if (tid < 8) {
        const unsigned tgt = n * 8u;
        volatile unsigned* p = &g_cnt[dir][tid][0];
        while ((int)(*p - tgt) < 0) { }
    }
    __syncthreads();
}

// ---------------------------------------------------------------------------
// Kernel 2: persistent bidirectional LSTM recurrence.
// Octet compute mapping (crossbar-optimal): warp w owns batches 8w..8w+7;
// lane (q, jg): b = 8w+q, j = jg*4..jg*4+3. h LDS.128 = 8 rows x 4-lane
// broadcast = 1 wavefront. W j-major padded stride 260: 4 distinct j rows
// per load hit distinct banks = 1 wavefront; k-pairs come packed for free
// (no dup2). h loads: R8-proven chunked __ldcg register double-buffer with
// block-wide syncthreads (generic proxy — no async visibility races).
// ---------------------------------------------------------------------------
__global__ void lstm_recur_kernel(const float* __restrict__ Whh_f,
                                  const float* __restrict__ Whh_b) {
    const int dir = blockIdx.x >> 6;
    const int blk = blockIdx.x & 63;
    const float* __restrict__ Whh = dir ? Whh_b : Whh_f;

    __shared__ float sW[16][260];   // j-major stationary weights, padded
    __shared__ float sh[64][68];    // h chunk (8 rows/warp, stride 17 units)
    __shared__ float sG[64][17];    // gates
    __shared__ float sC[64][4];     // cell state

    const int tid = threadIdx.x;
    const int wid = tid >> 5;
    const int lane = tid & 31;

    // Load stationary W: sW[jl][k] = Whh[(jl>>2)*256 + blk*4 + (jl&3)][k]
    for (int i = tid; i < 4096; i += 256) {
        int jl = i >> 8, k = i & 255;
        sW[jl][k] = Whh[(size_t)(((jl >> 2) << 8) + (blk << 2) + (jl & 3)) * Hn + k];
    }
    {
        sC[tid >> 2][tid & 3] = 0.0f;
        g_hstate[0][dir][blk * 256 + tid] = 0.0f;
    }
    dir_barrier(dir, blk, 1u);

    // octet compute mapping
    const int bl = wid * 8 + (lane >> 2);   // this lane's batch
    const int jbase = (lane & 3) * 4;       // this lane's 4 j rows
    // update mapping
    const int ub = tid >> 2, ur = tid & 3;
    // loader mapping (4 float4 per thread per chunk)
    const int lb0 = tid >> 4;             const int lk0 = (tid & 15) * 4;
    const int lb1 = (tid + 256) >> 4;
    const int lb2 = (tid + 512) >> 4;
    const int lb3 = (tid + 768) >> 4;

    // prefetch X for step 0
    const int s_first = dir ? 511 : 0;
    float4 xv = *reinterpret_cast<const float4*>(
        &g_Xperm[(((size_t)dir * Sn + s_first) * 64 + blk) * 1024 + tid * 4]);

    for (int step = 0; step < 512; step++) {
        const int s = dir ? (511 - step) : step;
        const int par = step & 1;
        const float* __restrict__ hin = g_hstate[par][dir];
        float* __restrict__ hout = g_hstate[par ^ 1][dir];

        // deposit prefetched X tile into sG (gate accumulator base)
        {
            int bb = tid >> 2, jl = (tid & 3) * 4;
            sG[bb][jl + 0] = xv.x; sG[bb][jl + 1] = xv.y;
            sG[bb][jl + 2] = xv.z; sG[bb][jl + 3] = xv.w;
        }

        // issue h chunk-0 loads
        float4 r0 = __ldcg(reinterpret_cast<const float4*>(&hin[lb0 * 256 + 0 + lk0]));
        float4 r1 = __ldcg(reinterpret_cast<const float4*>(&hin[lb1 * 256 + 0 + lk0]));
        float4 r2 = __ldcg(reinterpret_cast<const float4*>(&hin[lb2 * 256 + 0 + lk0]));
        float4 r3 = __ldcg(reinterpret_cast<const float4*>(&hin[lb3 * 256 + 0 + lk0]));

        unsigned long long A0 = 0ull, A1 = 0ull, A2 = 0ull, A3 = 0ull;
#pragma unroll
        for (int kc = 0; kc < 4; kc++) {
            // deposit regs into sh
            *reinterpret_cast<float4*>(&sh[lb0][lk0]) = r0;
            *reinterpret_cast<float4*>(&sh[lb1][lk0]) = r1;
            *reinterpret_cast<float4*>(&sh[lb2][lk0]) = r2;
            *reinterpret_cast<float4*>(&sh[lb3][lk0]) = r3;
            __syncthreads();
            const int kb = kc << 6;
            if (kc < 3) {
                const int kn = kb + 64;
                r0 = __ldcg(reinterpret_cast<const float4*>(&hin[lb0 * 256 + kn + lk0]));
                r1 = __ldcg(reinterpret_cast<const float4*>(&hin[lb1 * 256 + kn + lk0]));
                r2 = __ldcg(reinterpret_cast<const float4*>(&hin[lb2 * 256 + kn + lk0]));
                r3 = __ldcg(reinterpret_cast<const float4*>(&hin[lb3 * 256 + kn + lk0]));
            } else if (step < 511) {
                const int sn = dir ? (510 - step) : (step + 1);
                xv = *reinterpret_cast<const float4*>(
                    &g_Xperm[(((size_t)dir * Sn + sn) * 64 + blk) * 1024 + tid * 4]);
            }
#pragma unroll
            for (int kk = 0; kk < 16; kk++) {
                // h: 1 LDS.128, 8 distinct rows x 4-lane broadcast = 1 wf
                ulonglong2 hv = *reinterpret_cast<const ulonglong2*>(&sh[bl][kk * 4]);
                // W: 4 LDS.128, 4 distinct padded rows = 1 wf each
                ulonglong2 w0 = *reinterpret_cast<const ulonglong2*>(&sW[jbase + 0][kb + kk * 4]);
                ulonglong2 w1 = *reinterpret_cast<const ulonglong2*>(&sW[jbase + 1][kb + kk * 4]);
                ulonglong2 w2 = *reinterpret_cast<const ulonglong2*>(&sW[jbase + 2][kb + kk * 4]);
                ulonglong2 w3 = *reinterpret_cast<const ulonglong2*>(&sW[jbase + 3][kb + kk * 4]);
                ffma2(A0, hv.x, w0.x); ffma2(A0, hv.y, w0.y);
                ffma2(A1, hv.x, w1.x); ffma2(A1, hv.y, w1.y);
                ffma2(A2, hv.x, w2.x); ffma2(A2, hv.y, w2.y);
                ffma2(A3, hv.x, w3.x); ffma2(A3, hv.y, w3.y);
            }
            __syncthreads();
        }
        // epilogue: accumulate into gates (distinct (b,j) per lane)
        sG[bl][jbase + 0] += hsum2(A0);
        sG[bl][jbase + 1] += hsum2(A1);
        sG[bl][jbase + 2] += hsum2(A2);
        sG[bl][jbase + 3] += hsum2(A3);
        __syncthreads();

        // pointwise LSTM cell update
        {
            float gi = sG[ub][0 + ur];
            float gf = sG[ub][4 + ur];
            float gg = sG[ub][8 + ur];
            float go = sG[ub][12 + ur];
            float c = sC[ub][ur];
            c = fsig(gf) * c + fsig(gi) * ftanh(gg);
            float h = fsig(go) * ftanh(c);
            sC[ub][ur] = c;
            const int hcol = (blk << 2) + ur;
            hout[ub * 256 + hcol] = h;
            g_Hbuf[(((size_t)dir * Sn + s) * Bn + ub) * Hn + hcol] = h;
        }
        if (step < 511) dir_barrier(dir, blk, 2u + (unsigned)step);
    }

    // Reset barrier counters for the next launch: last block out does it.
    __syncthreads();
    if (tid == 0) {
        unsigned e = atomicAdd(&g_exit[dir], 1u);
        if (e == 63u) {
#pragma unroll
            for (int i = 0; i < 8; i++) g_cnt[dir][i][0] = 0u;
            g_exit[dir] = 0u;
        }
    }
}

// ---------------------------------------------------------------------------
// Kernel 3: emissions em[b][s][l] = [hf,hb] @ Wo + bo. One warp per (s,b).
// ---------------------------------------------------------------------------
__global__ void emissions_kernel(const float* __restrict__ Wo,
                                 const float* __restrict__ bo) {
    const int warp = (blockIdx.x * blockDim.x + threadIdx.x) >> 5;
    const int lane = threadIdx.x & 31;
    if (warp >= Bn * Sn) return;
    const int s = warp >> 6;
    const int b = warp & 63;
    const float* __restrict__ hf = &g_Hbuf[(((size_t)0 * Sn + s) * Bn + b) * Hn];
    const float* __restrict__ hb = &g_Hbuf[(((size_t)1 * Sn + s) * Bn + b) * Hn];

    float acc[9];
#pragma unroll
    for (int j = 0; j < 9; j++) acc[j] = 0.0f;

    for (int k = lane; k < 256; k += 32) {
        float vf = hf[k];
        float vb = hb[k];
        const float* w1 = &Wo[(size_t)k * Ln];
        const float* w2 = &Wo[(size_t)(256 + k) * Ln];
#pragma unroll
        for (int j = 0; j < 9; j++) acc[j] += vf * w1[j] + vb * w2[j];
    }
#pragma unroll
    for (int j = 0; j < 9; j++) {
        float v = acc[j];
#pragma unroll
        for (int o = 16; o; o >>= 1) v += __shfl_down_sync(0xffffffffu, v, o);
        if (lane == 0) g_em[((size_t)b * Sn + s) * Ln + j] = v + bo[j];
    }
}

// ---------------------------------------------------------------------------
// Kernel 4: CRF forward (register alpha + shfl broadcast) and gold score
// (t-parallel). One warp per batch.
// ---------------------------------------------------------------------------
__global__ void crf_kernel(const int* __restrict__ x,
                           const int* __restrict__ y,
                           const float* __restrict__ T,
                           const float* __restrict__ start,
                           const float* __restrict__ end) {
    const int b = blockIdx.x;
    const int lane = threadIdx.x;
    const float* __restrict__ em = &g_em[(size_t)b * Sn * Ln];
    const int* __restrict__ xb = &x[b * Sn];
    const int* __restrict__ yb = &y[b * Sn];
    const bool act = lane < 9;

    float Tcol[9];
    if (act) {
#pragma unroll
        for (int i = 0; i < 9; i++) Tcol[i] = T[i * 9 + lane];
    }
    float alpha = act ? (start[lane] + em[lane]) : -1e30f;

    for (int t = 1; t < Sn; t++) {
        int xt = __ldg(&xb[t]);
        float emt = act ? __ldg(&em[t * Ln + lane]) : 0.0f;
        float ai[9];
#pragma unroll
        for (int i = 0; i < 9; i++) ai[i] = __shfl_sync(0xffffffffu, alpha, i);
        if (xt != 0) {
            float v[9];
#pragma unroll
            for (int i = 0; i < 9; i++) v[i] = ai[i] + Tcol[i];
            float m01 = fmaxf(v[0], v[1]), m23 = fmaxf(v[2], v[3]);
            float m45 = fmaxf(v[4], v[5]), m67 = fmaxf(v[6], v[7]);
            float mx = fmaxf(fmaxf(fmaxf(m01, m23), fmaxf(m45, m67)), v[8]);
            float ssum = 0.0f;
#pragma unroll
            for (int i = 0; i < 9; i++) ssum += __expf(v[i] - mx);
            float na = mx + __logf(ssum) + emt;
            if (act) alpha = na;
        }
    }

    // logZ = logsumexp over 9 labels
    float vz = act ? (alpha + end[lane]) : -1e30f;
    float mx = vz;
#pragma unroll
    for (int o = 16; o; o >>= 1) mx = fmaxf(mx, __shfl_xor_sync(0xffffffffu, mx, o));
    float e = act ? __expf(vz - mx) : 0.0f;
#pragma unroll
    for (int o = 16; o; o >>= 1) e += __shfl_xor_sync(0xffffffffu, e, o);
    float logZ = mx + __logf(e);

    // gold score: t-parallel
    float gs = 0.0f;
    int cnt = 0;
    for (int t = lane; t < Sn; t += 32) {
        int m = (__ldg(&xb[t]) != 0) ? 1 : 0;
        cnt += m;
        if (t >= 1 && m) {
            int yt = __ldg(&yb[t]);
            int yp = __ldg(&yb[t - 1]);
            gs += T[yp * 9 + yt] + em[t * Ln + yt];
        }
    }
#pragma unroll
    for (int o = 16; o; o >>= 1) {
        gs  += __shfl_xor_sync(0xffffffffu, gs, o);
        cnt += __shfl_xor_sync(0xffffffffu, cnt, o);
    }

    if (lane == 0) {
        int y0 = yb[0];
        float score = start[y0] + em[y0] + gs;
        int last = cnt - 1;
        if (last < 0) last = 0;
        score += end[yb[last]];
        g_res[b] = logZ - score;
    }
}

// ---------------------------------------------------------------------------
// Kernel 5: mean over batch -> scalar output
// ---------------------------------------------------------------------------
__global__ void reduce_kernel(float* __restrict__ out) {
    __shared__ float s[64];
    s[threadIdx.x] = g_res[threadIdx.x];
    __syncthreads();
    if (threadIdx.x == 0) {
        float t = 0.0f;
        for (int i = 0; i < 64; i++) t += s[i];
        out[0] = t * (1.0f / 64.0f);
    }
}

// ---------------------------------------------------------------------------
extern "C" void kernel_launch(void* const* d_in, const int* in_sizes, int n_in,
                              void* d_out, int out_size) {
    const int*   x      = (const int*)  d_in[0];
    const int*   y      = (const int*)  d_in[1];
    const float* E      = (const float*)d_in[2];
    const float* Wih_f  = (const float*)d_in[3];
    const float* Whh_f  = (const float*)d_in[4];
    const float* b_f    = (const float*)d_in[5];
    const float* Wih_b  = (const float*)d_in[6];
    const float* Whh_b  = (const float*)d_in[7];
    const float* b_b    = (const float*)d_in[8];
    const float* Wo     = (const float*)d_in[9];
    const float* bo     = (const float*)d_in[10];
    const float* T      = (const float*)d_in[11];
    const float* start  = (const float*)d_in[12];
    const float* end    = (const float*)d_in[13];
    float* out = (float*)d_out;

    // Two dummies shift the ncu capture slot onto lstm_recur.
    dummy_kernel<<<1, 32>>>();
    dummy_kernel<<<1, 32>>>();
    dim3 gemm_grid(8, 512, 2);
    embed_inproj_kernel<<<gemm_grid, 256>>>(x, E, Wih_f, b_f, Wih_b, b_b);
    lstm_recur_kernel<<<128, 256>>>(Whh_f, Whh_b);
    emissions_kernel<<<4096, 256>>>(Wo, bo);
    crf_kernel<<<64, 32>>>(x, y, T, start, end);
    reduce_kernel<<<1, 64>>>(out);
}

// round 11
// speedup vs baseline: 1.4565x; 1.4565x over previous
#include <cuda_runtime.h>
#include <cuda_bf16.h>
#include <cstdint>

// Problem constants
#define Bn 64
#define Sn 512
#define Dn 256
#define Hn 256
#define Ln 9

// ---------------------------------------------------------------------------
// Static device scratch
// ---------------------------------------------------------------------------
__device__ float g_Xperm[2u * 512u * 64u * 1024u];      // 268 MB
__device__ float g_Hbuf[2u * 512u * 64u * 256u];        // 67 MB
__device__ float g_em[(size_t)Bn * Sn * Ln];
__device__ float g_res[Bn];
// Split barrier counters: 8 per direction, each on its own 128B line.
__device__ unsigned g_cnt[2][8][32];
__device__ unsigned g_exit[2];

__device__ __forceinline__ float fsig(float x) { return 1.0f / (1.0f + __expf(-x)); }
__device__ __forceinline__ float ftanh(float x) { return 2.0f / (1.0f + __expf(-2.0f * x)) - 1.0f; }

// Packed f32x2 FMA (sm_100+): d = a*b + d, lane-wise on 2 packed floats.
__device__ __forceinline__ void ffma2(unsigned long long& d,
                                      unsigned long long a,
                                      unsigned long long b) {
    asm("fma.rn.f32x2 %0, %1, %2, %0;" : "+l"(d) : "l"(a), "l"(b));
}
__device__ __forceinline__ unsigned long long dup2(float x) {
    unsigned long long r;
    asm("mov.b64 %0, {%1, %1};" : "=l"(r) : "f"(x));
    return r;
}
__device__ __forceinline__ float hsum2(unsigned long long p) {
    float lo, hi;
    asm("mov.b64 {%0, %1}, %2;" : "=f"(lo), "=f"(hi) : "l"(p));
    return lo + hi;
}

// ---------------------------------------------------------------------------
// Dummy kernels: shift the ncu capture slot onto the recurrence kernel.
// ---------------------------------------------------------------------------
__global__ void dummy_kernel() {}

// ---------------------------------------------------------------------------
// Kernel 1: embedding gather + input projection GEMM (+bias), permuted write.
// Tile 64m x 128n, K-chunk 16, 256 threads, 4x8 micro-tile, packed FFMA2.
// grid = (8 n-tiles, 512 s, 2 dirs)
// ---------------------------------------------------------------------------
__global__ void embed_inproj_kernel(const int* __restrict__ x,
                                    const float* __restrict__ E,
                                    const float* __restrict__ Wih_f,
                                    const float* __restrict__ b_f,
                                    const float* __restrict__ Wih_b,
                                    const float* __restrict__ b_b) {
    const int dir = blockIdx.z;
    const float* __restrict__ W = dir ? Wih_b : Wih_f;
    const float* __restrict__ bias = dir ? b_b : b_f;
    const int s = blockIdx.y;
    const int n0 = blockIdx.x * 128;

    __shared__ float sA[16][68];     // A^T: [k][m], 64 m + pad
    __shared__ float sB[16][132];    // B^T: [k][n], 128 n + pad
    __shared__ int srow[64];

    const int tid = threadIdx.x;
    if (tid < 64) srow[tid] = x[tid * Sn + s];
    __syncthreads();

    const int tm = tid & 15;          // 4 m-rows: 4*tm..
    const int tn = tid >> 4;          // 8 n-cols: 8*tn..
    const int lrow = tid >> 2;        // loader row 0..63
    const int kq = tid & 3;           // loader k-quad

    unsigned long long acc[4][4];     // [m][n-pair], each packs 2 n-values
#pragma unroll
    for (int c = 0; c < 4; c++)
#pragma unroll
        for (int p = 0; p < 4; p++) acc[c][p] = 0ull;

    for (int k0 = 0; k0 < 256; k0 += 16) {
        float4 a4 = *reinterpret_cast<const float4*>(&E[(size_t)srow[lrow] * Dn + k0 + kq * 4]);
        float4 b4 = *reinterpret_cast<const float4*>(&W[(size_t)(n0 + lrow) * Dn + k0 + kq * 4]);
        float4 c4 = *reinterpret_cast<const float4*>(&W[(size_t)(n0 + 64 + lrow) * Dn + k0 + kq * 4]);
        __syncthreads();   // previous compute done reading smem
        sA[kq * 4 + 0][lrow] = a4.x; sA[kq * 4 + 1][lrow] = a4.y;
        sA[kq * 4 + 2][lrow] = a4.z; sA[kq * 4 + 3][lrow] = a4.w;
        sB[kq * 4 + 0][lrow] = b4.x; sB[kq * 4 + 1][lrow] = b4.y;
        sB[kq * 4 + 2][lrow] = b4.z; sB[kq * 4 + 3][lrow] = b4.w;
        sB[kq * 4 + 0][64 + lrow] = c4.x; sB[kq * 4 + 1][64 + lrow] = c4.y;
        sB[kq * 4 + 2][64 + lrow] = c4.z; sB[kq * 4 + 3][64 + lrow] = c4.w;
        __syncthreads();
#pragma unroll
        for (int kk = 0; kk < 16; kk++) {
            float4 ra = *reinterpret_cast<float4*>(&sA[kk][4 * tm]);
            ulonglong2 rb0 = *reinterpret_cast<ulonglong2*>(&sB[kk][8 * tn]);
            ulonglong2 rb1 = *reinterpret_cast<ulonglong2*>(&sB[kk][8 * tn + 4]);
            unsigned long long d0 = dup2(ra.x), d1 = dup2(ra.y);
            unsigned long long d2 = dup2(ra.z), d3 = dup2(ra.w);
            ffma2(acc[0][0], d0, rb0.x); ffma2(acc[0][1], d0, rb0.y);
            ffma2(acc[0][2], d0, rb1.x); ffma2(acc[0][3], d0, rb1.y);
            ffma2(acc[1][0], d1, rb0.x); ffma2(acc[1][1], d1, rb0.y);
            ffma2(acc[1][2], d1, rb1.x); ffma2(acc[1][3], d1, rb1.y);
            ffma2(acc[2][0], d2, rb0.x); ffma2(acc[2][1], d2, rb0.y);
            ffma2(acc[2][2], d2, rb1.x); ffma2(acc[2][3], d2, rb1.y);
            ffma2(acc[3][0], d3, rb0.x); ffma2(acc[3][1], d3, rb0.y);
            ffma2(acc[3][2], d3, rb1.x); ffma2(acc[3][3], d3, rb1.y);
        }
    }

    // Epilogue: add bias, permuted write. n-range: n0 + 8*tn .. +7.
    const int nb = n0 + 8 * tn;
    const int blkA = (nb >> 2) & 63;  const int mgA = nb >> 8;
    const int nb2 = nb + 4;
    const int blkB = (nb2 >> 2) & 63; const int mgB = nb2 >> 8;
    const size_t baseA = (((size_t)dir * Sn + s) * 64 + blkA) * 1024 + (size_t)mgA * 4;
    const size_t baseB = (((size_t)dir * Sn + s) * 64 + blkB) * 1024 + (size_t)mgB * 4;
    float4 biasA = *reinterpret_cast<const float4*>(&bias[nb]);
    float4 biasB = *reinterpret_cast<const float4*>(&bias[nb + 4]);
#pragma unroll
    for (int c = 0; c < 4; c++) {
        const int b = 4 * tm + c;
        float f0, f1, f2, f3, f4, f5, f6, f7;
        asm("mov.b64 {%0, %1}, %2;" : "=f"(f0), "=f"(f1) : "l"(acc[c][0]));
        asm("mov.b64 {%0, %1}, %2;" : "=f"(f2), "=f"(f3) : "l"(acc[c][1]));
        asm("mov.b64 {%0, %1}, %2;" : "=f"(f4), "=f"(f5) : "l"(acc[c][2]));
        asm("mov.b64 {%0, %1}, %2;" : "=f"(f6), "=f"(f7) : "l"(acc[c][3]));
        float4 vA, vB;
        vA.x = f0 + biasA.x; vA.y = f1 + biasA.y; vA.z = f2 + biasA.z; vA.w = f3 + biasA.w;
        vB.x = f4 + biasB.x; vB.y = f5 + biasB.y; vB.z = f6 + biasB.z; vB.w = f7 + biasB.w;
        *reinterpret_cast<float4*>(&g_Xperm[baseA + (size_t)b * 16]) = vA;
        *reinterpret_cast<float4*>(&g_Xperm[baseB + (size_t)b * 16]) = vB;
    }
}

// ---------------------------------------------------------------------------
// Split-counter grid barrier (per direction, 64 blocks).
// ---------------------------------------------------------------------------
__device__ __forceinline__ void dir_barrier(int dir, int blk, unsigned n) {
    __threadfence();
    __syncthreads();
    const int tid = threadIdx.x;
    if (tid == 0) atomicAdd(&g_cnt[dir][blk & 7][0], 1u);
    if (tid < 8) {
        const unsigned tgt = n * 8u;
        volatile unsigned* p = &g_cnt[dir][tid][0];
        while ((int)(*p - tgt) < 0) { }
    }
    __syncthreads();
}

// ---------------------------------------------------------------------------
// Kernel 2: persistent bidirectional LSTM recurrence — gate-owner mapping.
// 128 blocks (64/dir), 256 threads = 8 warps. Block (dir,blk) owns gate rows
// {m*256 + blk*4 + r}. Lane (wid, q=lane>>2, r=lane&3) owns cell
// (b = 8*wid+q, hidden col r) and ALL FOUR of its gates:
//   - h LDS.128: 8 rows x 4-lane broadcast = 1 wavefront
//   - W LDS.128 per gate m: 4 consecutive rows {4m..4m+3} x 8-lane
//     broadcast, stride 260 (=4 mod 32) -> disjoint bank quads = 1 wf
//   - cell state c lives in a REGISTER for all 512 steps
//   - X read per-lane from global (4 LDG.32, prefetched under barrier)
//   - h written once to g_Hbuf; next step reads it back via __ldcg
//     (no separate hstate double buffer)
//   - step 0 skips the h.W product entirely (h0 = 0): no init barrier
// h chunk loads: R8-proven __ldcg register double-buffer, block syncthreads.
// ---------------------------------------------------------------------------
__global__ void lstm_recur_kernel(const float* __restrict__ Whh_f,
                                  const float* __restrict__ Whh_b) {
    const int dir = blockIdx.x >> 6;
    const int blk = blockIdx.x & 63;
    const float* __restrict__ Whh = dir ? Whh_b : Whh_f;

    __shared__ float sW[16][260];   // j-major, stride 260 (16B aligned, =4 mod 32)
    __shared__ float sh[64][68];    // h chunk [b][k], stride 68

    const int tid = threadIdx.x;
    const int lane = tid & 31;

    // Load stationary W: sW[jl][k] = Whh[(jl>>2)*256 + blk*4 + (jl&3)][k]
    for (int i = tid; i < 4096; i += 256) {
        int jl = i >> 8, k = i & 255;
        sW[jl][k] = Whh[(size_t)(((jl >> 2) << 8) + (blk << 2) + (jl & 3)) * Hn + k];
    }
    __syncthreads();

    // gate-owner mapping
    const int bl = ((tid >> 5) << 3) + (lane >> 2);  // this lane's batch
    const int r = lane & 3;                          // this lane's hidden col
    // loader mapping (4 float4 per thread per chunk)
    const int lb0 = tid >> 4;             const int lk0 = (tid & 15) * 4;
    const int lb1 = (tid + 256) >> 4;
    const int lb2 = (tid + 512) >> 4;
    const int lb3 = (tid + 768) >> 4;

    // per-lane X offset within an s-slice tile
    const int xoff = bl * 16 + r;

    // prefetch X for step 0
    const int s_first = dir ? 511 : 0;
    const float* Xt0 = &g_Xperm[(((size_t)dir * Sn + s_first) * 64 + blk) * 1024];
    float x0 = __ldg(&Xt0[xoff + 0]);
    float x1 = __ldg(&Xt0[xoff + 4]);
    float x2 = __ldg(&Xt0[xoff + 8]);
    float x3 = __ldg(&Xt0[xoff + 12]);

    float c = 0.0f;
    const int hcol = (blk << 2) + r;

    for (int step = 0; step < 512; step++) {
        const int s = dir ? (511 - step) : step;

        float g0 = x0, g1 = x1, g2 = x2, g3 = x3;

        if (step > 0) {
            const int sprev = dir ? (s + 1) : (s - 1);
            const float* __restrict__ hin =
                &g_Hbuf[((size_t)dir * Sn + sprev) * (Bn * Hn)];

            // issue h chunk-0 loads
            float4 r0 = __ldcg(reinterpret_cast<const float4*>(&hin[lb0 * 256 + 0 + lk0]));
            float4 r1 = __ldcg(reinterpret_cast<const float4*>(&hin[lb1 * 256 + 0 + lk0]));
            float4 r2 = __ldcg(reinterpret_cast<const float4*>(&hin[lb2 * 256 + 0 + lk0]));
            float4 r3 = __ldcg(reinterpret_cast<const float4*>(&hin[lb3 * 256 + 0 + lk0]));

            unsigned long long A0 = 0ull, A1 = 0ull, A2 = 0ull, A3 = 0ull;
#pragma unroll
            for (int kc = 0; kc < 4; kc++) {
                // deposit regs into sh
                *reinterpret_cast<float4*>(&sh[lb0][lk0]) = r0;
                *reinterpret_cast<float4*>(&sh[lb1][lk0]) = r1;
                *reinterpret_cast<float4*>(&sh[lb2][lk0]) = r2;
                *reinterpret_cast<float4*>(&sh[lb3][lk0]) = r3;
                __syncthreads();
                const int kb = kc << 6;
                if (kc < 3) {
                    const int kn = kb + 64;
                    r0 = __ldcg(reinterpret_cast<const float4*>(&hin[lb0 * 256 + kn + lk0]));
                    r1 = __ldcg(reinterpret_cast<const float4*>(&hin[lb1 * 256 + kn + lk0]));
                    r2 = __ldcg(reinterpret_cast<const float4*>(&hin[lb2 * 256 + kn + lk0]));
                    r3 = __ldcg(reinterpret_cast<const float4*>(&hin[lb3 * 256 + kn + lk0]));
                }
#pragma unroll
                for (int kk = 0; kk < 16; kk++) {
                    // h: 1 wf (8 rows x 4-lane broadcast)
                    ulonglong2 hv = *reinterpret_cast<const ulonglong2*>(&sh[bl][kk * 4]);
                    // W: 4 loads, each 4 consecutive rows x 8-lane bcast = 1 wf
                    ulonglong2 w0 = *reinterpret_cast<const ulonglong2*>(&sW[r + 0][kb + kk * 4]);
                    ulonglong2 w1 = *reinterpret_cast<const ulonglong2*>(&sW[r + 4][kb + kk * 4]);
                    ulonglong2 w2 = *reinterpret_cast<const ulonglong2*>(&sW[r + 8][kb + kk * 4]);
                    ulonglong2 w3 = *reinterpret_cast<const ulonglong2*>(&sW[r + 12][kb + kk * 4]);
                    ffma2(A0, hv.x, w0.x); ffma2(A0, hv.y, w0.y);
                    ffma2(A1, hv.x, w1.x); ffma2(A1, hv.y, w1.y);
                    ffma2(A2, hv.x, w2.x); ffma2(A2, hv.y, w2.y);
                    ffma2(A3, hv.x, w3.x); ffma2(A3, hv.y, w3.y);
                }
                __syncthreads();
            }
            g0 += hsum2(A0);
            g1 += hsum2(A1);
            g2 += hsum2(A2);
            g3 += hsum2(A3);
        }

        // lane-private LSTM cell update (gates: g0=i, g1=f, g2=g, g3=o)
        c = fsig(g1) * c + fsig(g0) * ftanh(g2);
        float h = fsig(g3) * ftanh(c);
        g_Hbuf[(((size_t)dir * Sn + s) * Bn + bl) * Hn + hcol] = h;

        // prefetch X for next step (latency hidden behind the barrier)
        if (step < 511) {
            const int sn = dir ? (510 - step) : (step + 1);
            const float* Xt = &g_Xperm[(((size_t)dir * Sn + sn) * 64 + blk) * 1024];
            x0 = __ldg(&Xt[xoff + 0]);
            x1 = __ldg(&Xt[xoff + 4]);
            x2 = __ldg(&Xt[xoff + 8]);
            x3 = __ldg(&Xt[xoff + 12]);
            dir_barrier(dir, blk, 1u + (unsigned)step);
        }
    }

    // Reset barrier counters for the next launch: last block out does it.
    __syncthreads();
    if (tid == 0) {
        unsigned e = atomicAdd(&g_exit[dir], 1u);
        if (e == 63u) {
#pragma unroll
            for (int i = 0; i < 8; i++) g_cnt[dir][i][0] = 0u;
            g_exit[dir] = 0u;
        }
    }
}

// ---------------------------------------------------------------------------
// Kernel 3: emissions em[b][s][l] = [hf,hb] @ Wo + bo. One warp per (s,b).
// ---------------------------------------------------------------------------
__global__ void emissions_kernel(const float* __restrict__ Wo,
                                 const float* __restrict__ bo) {
    const int warp = (blockIdx.x * blockDim.x + threadIdx.x) >> 5;
    const int lane = threadIdx.x & 31;
    if (warp >= Bn * Sn) return;
    const int s = warp >> 6;
    const int b = warp & 63;
    const float* __restrict__ hf = &g_Hbuf[(((size_t)0 * Sn + s) * Bn + b) * Hn];
    const float* __restrict__ hb = &g_Hbuf[(((size_t)1 * Sn + s) * Bn + b) * Hn];

    float acc[9];
#pragma unroll
    for (int j = 0; j < 9; j++) acc[j] = 0.0f;

    for (int k = lane; k < 256; k += 32) {
        float vf = hf[k];
        float vb = hb[k];
        const float* w1 = &Wo[(size_t)k * Ln];
        const float* w2 = &Wo[(size_t)(256 + k) * Ln];
#pragma unroll
        for (int j = 0; j < 9; j++) acc[j] += vf * w1[j] + vb * w2[j];
    }
#pragma unroll
    for (int j = 0; j < 9; j++) {
        float v = acc[j];
#pragma unroll
        for (int o = 16; o; o >>= 1) v += __shfl_down_sync(0xffffffffu, v, o);
        if (lane == 0) g_em[((size_t)b * Sn + s) * Ln + j] = v + bo[j];
    }
}

// ---------------------------------------------------------------------------
// Kernel 4: CRF forward (register alpha + shfl broadcast) and gold score
// (t-parallel). One warp per batch.
// ---------------------------------------------------------------------------
__global__ void crf_kernel(const int* __restrict__ x,
                           const int* __restrict__ y,
                           const float* __restrict__ T,
                           const float* __restrict__ start,
                           const float* __restrict__ end) {
    const int b = blockIdx.x;
    const int lane = threadIdx.x;
    const float* __restrict__ em = &g_em[(size_t)b * Sn * Ln];
    const int* __restrict__ xb = &x[b * Sn];
    const int* __restrict__ yb = &y[b * Sn];
    const bool act = lane < 9;

    float Tcol[9];
    if (act) {
#pragma unroll
        for (int i = 0; i < 9; i++) Tcol[i] = T[i * 9 + lane];
    }
    float alpha = act ? (start[lane] + em[lane]) : -1e30f;

    for (int t = 1; t < Sn; t++) {
        int xt = __ldg(&xb[t]);
        float emt = act ? __ldg(&em[t * Ln + lane]) : 0.0f;
        float ai[9];
#pragma unroll
        for (int i = 0; i < 9; i++) ai[i] = __shfl_sync(0xffffffffu, alpha, i);
        if (xt != 0) {
            float v[9];
#pragma unroll
            for (int i = 0; i < 9; i++) v[i] = ai[i] + Tcol[i];
            float m01 = fmaxf(v[0], v[1]), m23 = fmaxf(v[2], v[3]);
            float m45 = fmaxf(v[4], v[5]), m67 = fmaxf(v[6], v[7]);
            float mx = fmaxf(fmaxf(fmaxf(m01, m23), fmaxf(m45, m67)), v[8]);
            float ssum = 0.0f;
#pragma unroll
            for (int i = 0; i < 9; i++) ssum += __expf(v[i] - mx);
            float na = mx + __logf(ssum) + emt;
            if (act) alpha = na;
        }
    }

    // logZ = logsumexp over 9 labels
    float vz = act ? (alpha + end[lane]) : -1e30f;
    float mx = vz;
#pragma unroll
    for (int o = 16; o; o >>= 1) mx = fmaxf(mx, __shfl_xor_sync(0xffffffffu, mx, o));
    float e = act ? __expf(vz - mx) : 0.0f;
#pragma unroll
    for (int o = 16; o; o >>= 1) e += __shfl_xor_sync(0xffffffffu, e, o);
    float logZ = mx + __logf(e);

    // gold score: t-parallel
    float gs = 0.0f;
    int cnt = 0;
    for (int t = lane; t < Sn; t += 32) {
        int m = (__ldg(&xb[t]) != 0) ? 1 : 0;
        cnt += m;
        if (t >= 1 && m) {
            int yt = __ldg(&yb[t]);
            int yp = __ldg(&yb[t - 1]);
            gs += T[yp * 9 + yt] + em[t * Ln + yt];
        }
    }
#pragma unroll
    for (int o = 16; o; o >>= 1) {
        gs  += __shfl_xor_sync(0xffffffffu, gs, o);
        cnt += __shfl_xor_sync(0xffffffffu, cnt, o);
    }

    if (lane == 0) {
        int y0 = yb[0];
        float score = start[y0] + em[y0] + gs;
        int last = cnt - 1;
        if (last < 0) last = 0;
        score += end[yb[last]];
        g_res[b] = logZ - score;
    }
}

// ---------------------------------------------------------------------------
// Kernel 5: mean over batch -> scalar output
// ---------------------------------------------------------------------------
__global__ void reduce_kernel(float* __restrict__ out) {
    __shared__ float s[64];
    s[threadIdx.x] = g_res[threadIdx.x];
    __syncthreads();
    if (threadIdx.x == 0) {
        float t = 0.0f;
        for (int i = 0; i < 64; i++) t += s[i];
        out[0] = t * (1.0f / 64.0f);
    }
}

// ---------------------------------------------------------------------------
extern "C" void kernel_launch(void* const* d_in, const int* in_sizes, int n_in,
                              void* d_out, int out_size) {
    const int*   x      = (const int*)  d_in[0];
    const int*   y      = (const int*)  d_in[1];
    const float* E      = (const float*)d_in[2];
    const float* Wih_f  = (const float*)d_in[3];
    const float* Whh_f  = (const float*)d_in[4];
    const float* b_f    = (const float*)d_in[5];
    const float* Wih_b  = (const float*)d_in[6];
    const float* Whh_b  = (const float*)d_in[7];
    const float* b_b    = (const float*)d_in[8];
    const float* Wo     = (const float*)d_in[9];
    const float* bo     = (const float*)d_in[10];
    const float* T      = (const float*)d_in[11];
    const float* start  = (const float*)d_in[12];
    const float* end    = (const float*)d_in[13];
    float* out = (float*)d_out;

    // Two dummies shift the ncu capture slot onto lstm_recur.
    dummy_kernel<<<1, 32>>>();
    dummy_kernel<<<1, 32>>>();
    dim3 gemm_grid(8, 512, 2);
    embed_inproj_kernel<<<gemm_grid, 256>>>(x, E, Wih_f, b_f, Wih_b, b_b);
    lstm_recur_kernel<<<128, 256>>>(Whh_f, Whh_b);
    emissions_kernel<<<4096, 256>>>(Wo, bo);
    crf_kernel<<<64, 32>>>(x, y, T, start, end);
    reduce_kernel<<<1, 64>>>(out);
}

// round 12
// speedup vs baseline: 1.8437x; 1.2658x over previous
#include <cuda_runtime.h>
#include <cuda_bf16.h>
#include <cstdint>

// Problem constants
#define Bn 64
#define Sn 512
#define Dn 256
#define Hn 256
#define Ln 9

// ---------------------------------------------------------------------------
// Static device scratch
// ---------------------------------------------------------------------------
__device__ float g_Xperm[2u * 512u * 64u * 1024u];      // 268 MB
__device__ float g_Hbuf[2u * 512u * 64u * 256u];        // 67 MB
__device__ float g_hstate[2][2][Bn * Hn];               // [parity][dir]
__device__ float g_em[(size_t)Bn * Sn * Ln];
__device__ float g_res[Bn];
// Split barrier counters: 8 per direction, each on its own 128B line.
__device__ unsigned g_cnt[2][8][32];
__device__ unsigned g_exit[2];
// Producer-consumer readiness flags: 8 producer blocks per (dir, s) slice.
__device__ unsigned g_xready[2][512];

__device__ __forceinline__ float fsig(float x) { return 1.0f / (1.0f + __expf(-x)); }
__device__ __forceinline__ float ftanh(float x) { return 2.0f / (1.0f + __expf(-2.0f * x)) - 1.0f; }

// Packed f32x2 FMA (sm_100+): d = a*b + d, lane-wise on 2 packed floats.
__device__ __forceinline__ void ffma2(unsigned long long& d,
                                      unsigned long long a,
                                      unsigned long long b) {
    asm("fma.rn.f32x2 %0, %1, %2, %0;" : "+l"(d) : "l"(a), "l"(b));
}
__device__ __forceinline__ unsigned long long dup2(float x) {
    unsigned long long r;
    asm("mov.b64 %0, {%1, %1};" : "=l"(r) : "f"(x));
    return r;
}
__device__ __forceinline__ float hsum2(unsigned long long p) {
    float lo, hi;
    asm("mov.b64 {%0, %1}, %2;" : "=f"(lo), "=f"(hi) : "l"(p));
    return lo + hi;
}

// ---------------------------------------------------------------------------
// Dummy kernels: keep the ncu capture slot (launch #4) on the fused kernel.
// ---------------------------------------------------------------------------
__global__ void dummy_kernel() {}

// ---------------------------------------------------------------------------
// Reset kernel: zero the producer-consumer flags (runs before the fused
// kernel on every graph replay).
// ---------------------------------------------------------------------------
__global__ void reset_kernel() {
    ((unsigned*)g_xready)[threadIdx.x] = 0u;
}

// ---------------------------------------------------------------------------
// Split-counter grid barrier (per direction, 64 blocks).
// ---------------------------------------------------------------------------
__device__ __forceinline__ void dir_barrier(int dir, int blk, unsigned n) {
    __threadfence();
    __syncthreads();
    const int tid = threadIdx.x;
    if (tid == 0) atomicAdd(&g_cnt[dir][blk & 7][0], 1u);
    if (tid < 8) {
        const unsigned tgt = n * 8u;
        volatile unsigned* p = &g_cnt[dir][tid][0];
        while ((int)(*p - tgt) < 0) { }
    }
    __syncthreads();
}

// ---------------------------------------------------------------------------
// Fused kernel. Grid = 128 recurrence blocks + 8192 GEMM producer blocks.
// Dynamic smem 100KB/block caps occupancy at 2 blocks/SM; the 128
// recurrence blocks land on 128 distinct SMs (blockIdx order), GEMM blocks
// stream through the remaining slots concurrently.
//
// GEMM role (bid >= 128): embedding gather + input projection (R8 body),
//   production index p maps to s = p (fwd) / 511-p (bwd) so each direction's
//   slices are produced in its consumption order; flags 8 producers/slice.
// Recurrence role (bid < 128): R8-proven persistent LSTM body; polls the
//   flag for the NEXT step's slice between issuing chunk-0 h loads and the
//   compute loop (hidden in steady state).
// ---------------------------------------------------------------------------
__global__ void __launch_bounds__(256, 1)
fused_kernel(const int* __restrict__ x,
             const float* __restrict__ E,
             const float* __restrict__ Wih_f,
             const float* __restrict__ b_f,
             const float* __restrict__ Wih_b,
             const float* __restrict__ b_b,
             const float* __restrict__ Whh_f,
             const float* __restrict__ Whh_b) {
    extern __shared__ float dyn[];
    const int tid = threadIdx.x;

    if (blockIdx.x >= 128) {
        // =================== GEMM producer role ===================
        const int gid = blockIdx.x - 128;
        const int ntile = gid & 7;
        const int dirp = (gid >> 3) & 1;
        const int p = gid >> 4;                 // production index 0..511
        const int s = dirp ? (511 - p) : p;     // actual sequence slot

        const float* __restrict__ W = dirp ? Wih_b : Wih_f;
        const float* __restrict__ bias = dirp ? b_b : b_f;
        const int n0 = ntile * 128;

        float (*sA)[68] = (float(*)[68])dyn;                 // 1088 floats
        float (*sB)[132] = (float(*)[132])(dyn + 1088);      // 2112 floats
        int* srow = (int*)(dyn + 3200);

        if (tid < 64) srow[tid] = x[tid * Sn + s];
        __syncthreads();

        const int tm = tid & 15;
        const int tn = tid >> 4;
        const int lrow = tid >> 2;
        const int kq = tid & 3;

        unsigned long long acc[4][4];
#pragma unroll
        for (int c = 0; c < 4; c++)
#pragma unroll
            for (int q = 0; q < 4; q++) acc[c][q] = 0ull;

        for (int k0 = 0; k0 < 256; k0 += 16) {
            float4 a4 = *reinterpret_cast<const float4*>(&E[(size_t)srow[lrow] * Dn + k0 + kq * 4]);
            float4 b4 = *reinterpret_cast<const float4*>(&W[(size_t)(n0 + lrow) * Dn + k0 + kq * 4]);
            float4 c4 = *reinterpret_cast<const float4*>(&W[(size_t)(n0 + 64 + lrow) * Dn + k0 + kq * 4]);
            __syncthreads();
            sA[kq * 4 + 0][lrow] = a4.x; sA[kq * 4 + 1][lrow] = a4.y;
            sA[kq * 4 + 2][lrow] = a4.z; sA[kq * 4 + 3][lrow] = a4.w;
            sB[kq * 4 + 0][lrow] = b4.x; sB[kq * 4 + 1][lrow] = b4.y;
            sB[kq * 4 + 2][lrow] = b4.z; sB[kq * 4 + 3][lrow] = b4.w;
            sB[kq * 4 + 0][64 + lrow] = c4.x; sB[kq * 4 + 1][64 + lrow] = c4.y;
            sB[kq * 4 + 2][64 + lrow] = c4.z; sB[kq * 4 + 3][64 + lrow] = c4.w;
            __syncthreads();
#pragma unroll
            for (int kk = 0; kk < 16; kk++) {
                float4 ra = *reinterpret_cast<float4*>(&sA[kk][4 * tm]);
                ulonglong2 rb0 = *reinterpret_cast<ulonglong2*>(&sB[kk][8 * tn]);
                ulonglong2 rb1 = *reinterpret_cast<ulonglong2*>(&sB[kk][8 * tn + 4]);
                unsigned long long d0 = dup2(ra.x), d1 = dup2(ra.y);
                unsigned long long d2 = dup2(ra.z), d3 = dup2(ra.w);
                ffma2(acc[0][0], d0, rb0.x); ffma2(acc[0][1], d0, rb0.y);
                ffma2(acc[0][2], d0, rb1.x); ffma2(acc[0][3], d0, rb1.y);
                ffma2(acc[1][0], d1, rb0.x); ffma2(acc[1][1], d1, rb0.y);
                ffma2(acc[1][2], d1, rb1.x); ffma2(acc[1][3], d1, rb1.y);
                ffma2(acc[2][0], d2, rb0.x); ffma2(acc[2][1], d2, rb0.y);
                ffma2(acc[2][2], d2, rb1.x); ffma2(acc[2][3], d2, rb1.y);
                ffma2(acc[3][0], d3, rb0.x); ffma2(acc[3][1], d3, rb0.y);
                ffma2(acc[3][2], d3, rb1.x); ffma2(acc[3][3], d3, rb1.y);
            }
        }

        // Epilogue: add bias, permuted write, then publish readiness.
        const int nb = n0 + 8 * tn;
        const int blkA = (nb >> 2) & 63;  const int mgA = nb >> 8;
        const int nb2 = nb + 4;
        const int blkB = (nb2 >> 2) & 63; const int mgB = nb2 >> 8;
        const size_t baseA = (((size_t)dirp * Sn + s) * 64 + blkA) * 1024 + (size_t)mgA * 4;
        const size_t baseB = (((size_t)dirp * Sn + s) * 64 + blkB) * 1024 + (size_t)mgB * 4;
        float4 biasA = *reinterpret_cast<const float4*>(&bias[nb]);
        float4 biasB = *reinterpret_cast<const float4*>(&bias[nb + 4]);
#pragma unroll
        for (int c = 0; c < 4; c++) {
            const int b = 4 * tm + c;
            float f0, f1, f2, f3, f4, f5, f6, f7;
            asm("mov.b64 {%0, %1}, %2;" : "=f"(f0), "=f"(f1) : "l"(acc[c][0]));
            asm("mov.b64 {%0, %1}, %2;" : "=f"(f2), "=f"(f3) : "l"(acc[c][1]));
            asm("mov.b64 {%0, %1}, %2;" : "=f"(f4), "=f"(f5) : "l"(acc[c][2]));
            asm("mov.b64 {%0, %1}, %2;" : "=f"(f6), "=f"(f7) : "l"(acc[c][3]));
            float4 vA, vB;
            vA.x = f0 + biasA.x; vA.y = f1 + biasA.y; vA.z = f2 + biasA.z; vA.w = f3 + biasA.w;
            vB.x = f4 + biasB.x; vB.y = f5 + biasB.y; vB.z = f6 + biasB.z; vB.w = f7 + biasB.w;
            *reinterpret_cast<float4*>(&g_Xperm[baseA + (size_t)b * 16]) = vA;
            *reinterpret_cast<float4*>(&g_Xperm[baseB + (size_t)b * 16]) = vB;
        }
        __threadfence();
        __syncthreads();
        if (tid == 0) atomicAdd(&g_xready[dirp][s], 1u);
        return;
    }

    // =================== Recurrence role (R8-proven body) ===================
    const int dir = blockIdx.x >> 6;
    const int blk = blockIdx.x & 63;
    const float* __restrict__ Whh = dir ? Whh_b : Whh_f;

    float (*sW)[256] = (float(*)[256])dyn;                       // 4096 floats
    float (*sh)[68] = (float(*)[68])(dyn + 4096);                // 4352 floats
    float (*sG)[17] = (float(*)[17])(dyn + 4096 + 64 * 68);      // 1088 floats
    float (*sC)[4] = (float(*)[4])(dyn + 4096 + 64 * 68 + 64 * 17);

    for (int i = tid; i < 4096; i += 256) {
        int jl = i >> 8, k = i & 255;
        sW[jl][k] = Whh[(size_t)(((jl >> 2) << 8) + (blk << 2) + (jl & 3)) * Hn + k];
    }
    {
        int ub0 = tid >> 2, ur0 = tid & 3;
        sC[ub0][ur0] = 0.0f;
        g_hstate[0][dir][blk * 256 + tid] = 0.0f;
    }
    dir_barrier(dir, blk, 1u);

    // compute mapping: warp w handles j = 4*(w&3).., batches (w>>2)*32 + lane
    const int jq4 = ((tid >> 5) & 3) * 4;
    const int bh = ((tid >> 7) << 5) + (tid & 31);
    // update mapping
    const int ub = tid >> 2, ur = tid & 3;
    // loader mapping (4 float4 per thread per chunk)
    const int lb0 = tid >> 4;             const int lk0 = (tid & 15) * 4;
    const int lb1 = (tid + 256) >> 4;
    const int lb2 = (tid + 512) >> 4;
    const int lb3 = (tid + 768) >> 4;

    // wait for the first X slice, then prefetch it
    const int s_first = dir ? 511 : 0;
    {
        const unsigned* fl = &g_xready[dir][s_first];
        while (__ldcg(fl) < 8u) { }
    }
    float4 xv = *reinterpret_cast<const float4*>(
        &g_Xperm[(((size_t)dir * Sn + s_first) * 64 + blk) * 1024 + tid * 4]);

    for (int step = 0; step < 512; step++) {
        const int s = dir ? (511 - step) : step;
        const int par = step & 1;
        const float* __restrict__ hin = g_hstate[par][dir];
        float* __restrict__ hout = g_hstate[par ^ 1][dir];

        // deposit prefetched X tile into sG (gate accumulator base)
        {
            int bb = tid >> 2, jl = (tid & 3) * 4;
            sG[bb][jl + 0] = xv.x; sG[bb][jl + 1] = xv.y;
            sG[bb][jl + 2] = xv.z; sG[bb][jl + 3] = xv.w;
        }

        // issue h chunk-0 loads
        float4 r0 = __ldcg(reinterpret_cast<const float4*>(&hin[lb0 * 256 + 0 + lk0]));
        float4 r1 = __ldcg(reinterpret_cast<const float4*>(&hin[lb1 * 256 + 0 + lk0]));
        float4 r2 = __ldcg(reinterpret_cast<const float4*>(&hin[lb2 * 256 + 0 + lk0]));
        float4 r3 = __ldcg(reinterpret_cast<const float4*>(&hin[lb3 * 256 + 0 + lk0]));

        // ensure next step's X slice is produced before the kc==3 prefetch
        // (overlaps the in-flight chunk-0 loads; single L2 read when ready)
        if (step < 511) {
            const unsigned* fl = &g_xready[dir][dir ? (510 - step) : (step + 1)];
            if (__ldcg(fl) < 8u) {
                while (__ldcg(fl) < 8u) { }
            }
        }

        unsigned long long A0 = 0ull, A1 = 0ull, A2 = 0ull, A3 = 0ull;
#pragma unroll
        for (int kc = 0; kc < 4; kc++) {
            // deposit regs into sh
            *reinterpret_cast<float4*>(&sh[lb0][lk0]) = r0;
            *reinterpret_cast<float4*>(&sh[lb1][lk0]) = r1;
            *reinterpret_cast<float4*>(&sh[lb2][lk0]) = r2;
            *reinterpret_cast<float4*>(&sh[lb3][lk0]) = r3;
            __syncthreads();
            const int kb = kc << 6;
            if (kc < 3) {
                const int kn = kb + 64;
                r0 = __ldcg(reinterpret_cast<const float4*>(&hin[lb0 * 256 + kn + lk0]));
                r1 = __ldcg(reinterpret_cast<const float4*>(&hin[lb1 * 256 + kn + lk0]));
                r2 = __ldcg(reinterpret_cast<const float4*>(&hin[lb2 * 256 + kn + lk0]));
                r3 = __ldcg(reinterpret_cast<const float4*>(&hin[lb3 * 256 + kn + lk0]));
            } else if (step < 511) {
                const int sn = dir ? (510 - step) : (step + 1);
                xv = *reinterpret_cast<const float4*>(
                    &g_Xperm[(((size_t)dir * Sn + sn) * 64 + blk) * 1024 + tid * 4]);
            }
#pragma unroll
            for (int kk = 0; kk < 16; kk++) {
                ulonglong2 hv = *reinterpret_cast<const ulonglong2*>(&sh[bh][kk * 4]);
                ulonglong2 w0 = *reinterpret_cast<const ulonglong2*>(&sW[jq4 + 0][kb + kk * 4]);
                ulonglong2 w1 = *reinterpret_cast<const ulonglong2*>(&sW[jq4 + 1][kb + kk * 4]);
                ulonglong2 w2 = *reinterpret_cast<const ulonglong2*>(&sW[jq4 + 2][kb + kk * 4]);
                ulonglong2 w3 = *reinterpret_cast<const ulonglong2*>(&sW[jq4 + 3][kb + kk * 4]);
                ffma2(A0, hv.x, w0.x); ffma2(A0, hv.y, w0.y);
                ffma2(A1, hv.x, w1.x); ffma2(A1, hv.y, w1.y);
                ffma2(A2, hv.x, w2.x); ffma2(A2, hv.y, w2.y);
                ffma2(A3, hv.x, w3.x); ffma2(A3, hv.y, w3.y);
            }
            __syncthreads();
        }
        // epilogue: accumulate into gates (distinct (b,j) per thread)
        sG[bh][jq4 + 0] += hsum2(A0);
        sG[bh][jq4 + 1] += hsum2(A1);
        sG[bh][jq4 + 2] += hsum2(A2);
        sG[bh][jq4 + 3] += hsum2(A3);
        __syncthreads();

        // pointwise LSTM cell update
        {
            float gi = sG[ub][0 + ur];
            float gf = sG[ub][4 + ur];
            float gg = sG[ub][8 + ur];
            float go = sG[ub][12 + ur];
            float c = sC[ub][ur];
            c = fsig(gf) * c + fsig(gi) * ftanh(gg);
            float h = fsig(go) * ftanh(c);
            sC[ub][ur] = c;
            const int hcol = (blk << 2) + ur;
            hout[ub * 256 + hcol] = h;
            g_Hbuf[(((size_t)dir * Sn + s) * Bn + ub) * Hn + hcol] = h;
        }
        if (step < 511) dir_barrier(dir, blk, 2u + (unsigned)step);
    }

    // Reset barrier counters for the next launch: last block out does it.
    __syncthreads();
    if (tid == 0) {
        unsigned e = atomicAdd(&g_exit[dir], 1u);
        if (e == 63u) {
#pragma unroll
            for (int i = 0; i < 8; i++) g_cnt[dir][i][0] = 0u;
            g_exit[dir] = 0u;
        }
    }
}

// ---------------------------------------------------------------------------
// Kernel 3: emissions em[b][s][l] = [hf,hb] @ Wo + bo. One warp per (s,b).
// ---------------------------------------------------------------------------
__global__ void emissions_kernel(const float* __restrict__ Wo,
                                 const float* __restrict__ bo) {
    const int warp = (blockIdx.x * blockDim.x + threadIdx.x) >> 5;
    const int lane = threadIdx.x & 31;
    if (warp >= Bn * Sn) return;
    const int s = warp >> 6;
    const int b = warp & 63;
    const float* __restrict__ hf = &g_Hbuf[(((size_t)0 * Sn + s) * Bn + b) * Hn];
    const float* __restrict__ hb = &g_Hbuf[(((size_t)1 * Sn + s) * Bn + b) * Hn];

    float acc[9];
#pragma unroll
    for (int j = 0; j < 9; j++) acc[j] = 0.0f;

    for (int k = lane; k < 256; k += 32) {
        float vf = hf[k];
        float vb = hb[k];
        const float* w1 = &Wo[(size_t)k * Ln];
        const float* w2 = &Wo[(size_t)(256 + k) * Ln];
#pragma unroll
        for (int j = 0; j < 9; j++) acc[j] += vf * w1[j] + vb * w2[j];
    }
#pragma unroll
    for (int j = 0; j < 9; j++) {
        float v = acc[j];
#pragma unroll
        for (int o = 16; o; o >>= 1) v += __shfl_down_sync(0xffffffffu, v, o);
        if (lane == 0) g_em[((size_t)b * Sn + s) * Ln + j] = v + bo[j];
    }
}

// ---------------------------------------------------------------------------
// Kernel 4: CRF forward (register alpha + shfl broadcast) and gold score
// (t-parallel). One warp per batch.
// ---------------------------------------------------------------------------
__global__ void crf_kernel(const int* __restrict__ x,
                           const int* __restrict__ y,
                           const float* __restrict__ T,
                           const float* __restrict__ start,
                           const float* __restrict__ end) {
    const int b = blockIdx.x;
    const int lane = threadIdx.x;
    const float* __restrict__ em = &g_em[(size_t)b * Sn * Ln];
    const int* __restrict__ xb = &x[b * Sn];
    const int* __restrict__ yb = &y[b * Sn];
    const bool act = lane < 9;

    float Tcol[9];
    if (act) {
#pragma unroll
        for (int i = 0; i < 9; i++) Tcol[i] = T[i * 9 + lane];
    }
    float alpha = act ? (start[lane] + em[lane]) : -1e30f;

    for (int t = 1; t < Sn; t++) {
        int xt = __ldg(&xb[t]);
        float emt = act ? __ldg(&em[t * Ln + lane]) : 0.0f;
        float ai[9];
#pragma unroll
        for (int i = 0; i < 9; i++) ai[i] = __shfl_sync(0xffffffffu, alpha, i);
        if (xt != 0) {
            float v[9];
#pragma unroll
            for (int i = 0; i < 9; i++) v[i] = ai[i] + Tcol[i];
            float m01 = fmaxf(v[0], v[1]), m23 = fmaxf(v[2], v[3]);
            float m45 = fmaxf(v[4], v[5]), m67 = fmaxf(v[6], v[7]);
            float mx = fmaxf(fmaxf(fmaxf(m01, m23), fmaxf(m45, m67)), v[8]);
            float ssum = 0.0f;
#pragma unroll
            for (int i = 0; i < 9; i++) ssum += __expf(v[i] - mx);
            float na = mx + __logf(ssum) + emt;
            if (act) alpha = na;
        }
    }

    // logZ = logsumexp over 9 labels
    float vz = act ? (alpha + end[lane]) : -1e30f;
    float mx = vz;
#pragma unroll
    for (int o = 16; o; o >>= 1) mx = fmaxf(mx, __shfl_xor_sync(0xffffffffu, mx, o));
    float e = act ? __expf(vz - mx) : 0.0f;
#pragma unroll
    for (int o = 16; o; o >>= 1) e += __shfl_xor_sync(0xffffffffu, e, o);
    float logZ = mx + __logf(e);

    // gold score: t-parallel
    float gs = 0.0f;
    int cnt = 0;
    for (int t = lane; t < Sn; t += 32) {
        int m = (__ldg(&xb[t]) != 0) ? 1 : 0;
        cnt += m;
        if (t >= 1 && m) {
            int yt = __ldg(&yb[t]);
            int yp = __ldg(&yb[t - 1]);
            gs += T[yp * 9 + yt] + em[t * Ln + yt];
        }
    }
#pragma unroll
    for (int o = 16; o; o >>= 1) {
        gs  += __shfl_xor_sync(0xffffffffu, gs, o);
        cnt += __shfl_xor_sync(0xffffffffu, cnt, o);
    }

    if (lane == 0) {
        int y0 = yb[0];
        float score = start[y0] + em[y0] + gs;
        int last = cnt - 1;
        if (last < 0) last = 0;
        score += end[yb[last]];
        g_res[b] = logZ - score;
    }
}

// ---------------------------------------------------------------------------
// Kernel 5: mean over batch -> scalar output
// ---------------------------------------------------------------------------
__global__ void reduce_kernel(float* __restrict__ out) {
    __shared__ float s[64];
    s[threadIdx.x] = g_res[threadIdx.x];
    __syncthreads();
    if (threadIdx.x == 0) {
        float t = 0.0f;
        for (int i = 0; i < 64; i++) t += s[i];
        out[0] = t * (1.0f / 64.0f);
    }
}

// ---------------------------------------------------------------------------
extern "C" void kernel_launch(void* const* d_in, const int* in_sizes, int n_in,
                              void* d_out, int out_size) {
    const int*   x      = (const int*)  d_in[0];
    const int*   y      = (const int*)  d_in[1];
    const float* E      = (const float*)d_in[2];
    const float* Wih_f  = (const float*)d_in[3];
    const float* Whh_f  = (const float*)d_in[4];
    const float* b_f    = (const float*)d_in[5];
    const float* Wih_b  = (const float*)d_in[6];
    const float* Whh_b  = (const float*)d_in[7];
    const float* b_b    = (const float*)d_in[8];
    const float* Wo     = (const float*)d_in[9];
    const float* bo     = (const float*)d_in[10];
    const float* T      = (const float*)d_in[11];
    const float* start  = (const float*)d_in[12];
    const float* end    = (const float*)d_in[13];
    float* out = (float*)d_out;

    // 100KB dynamic smem: caps occupancy at 2 blocks/SM so the 128
    // recurrence blocks occupy distinct SMs; GEMM fills remaining slots.
    const int fused_smem = 100 * 1024;
    cudaFuncSetAttribute(fused_kernel,
                         cudaFuncAttributeMaxDynamicSharedMemorySize, fused_smem);

    // dummies keep the ncu capture slot (launch #4) on the fused kernel
    dummy_kernel<<<1, 32>>>();
    dummy_kernel<<<1, 32>>>();
    reset_kernel<<<1, 1024>>>();
    fused_kernel<<<128 + 8192, 256, fused_smem>>>(x, E, Wih_f, b_f, Wih_b, b_b,
                                                  Whh_f, Whh_b);
    emissions_kernel<<<4096, 256>>>(Wo, bo);
    crf_kernel<<<64, 32>>>(x, y, T, start, end);
    reduce_kernel<<<1, 64>>>(out);
}